// round 14
// baseline (speedup 1.0000x reference)
#include <cuda_runtime.h>
#include <cuda_bf16.h>
#include <cuda_fp16.h>
#include <cstdint>
#include <cstdio>

// ---------------------------------------------------------------------------
// Problem constants
// ---------------------------------------------------------------------------
#define NB    4
#define CIN   16
#define HIN   64
#define WIN   64
#define HF    32
#define WF    32
#define L     1024
#define D     1024
#define HEADS 16
#define DH    64
#define DEPTH 8
#define TOK   (NB*L)       // 4096
#define D3    (3*D)        // 3072
#define D4    (4*D)        // 4096

// ---------------------------------------------------------------------------
// Scratch (static device globals; no runtime allocation)
// ---------------------------------------------------------------------------
__device__ float g_patch[TOK * 64];
__device__ float g_tok  [TOK * D];
__device__ float g_h    [TOK * D];
__device__ __half g_qkvh[TOK * D3];

__device__ __half g_h_h  [TOK * D];     // fp16 rmsnorm output (GEMM A)
__device__ __half g_att_h[TOK * D];     // fp16 attention output
__device__ __half g_mlp_h[TOK * D4];    // fp16 gelu(fc1) output

// fp16 weights (all depths)
__device__ __half g_wqkv_h[DEPTH * D3 * D];
__device__ __half g_wproj_h[DEPTH * D * D];
__device__ __half g_wfc1_h[DEPTH * D4 * D];
__device__ __half g_wfc2_h[DEPTH * D * D4];

// RoPE table: [pos 0..31][t 0..15] -> (cos, sin)
__device__ float2 g_ropetab[32 * 16];

// ---------------------------------------------------------------------------
// Helpers
// ---------------------------------------------------------------------------
__device__ __forceinline__ uint32_t smem_u32(const void* p) {
    uint32_t a;
    asm("{ .reg .u64 t; cvta.to.shared.u64 t, %1; cvt.u32.u64 %0, t; }" : "=r"(a) : "l"(p));
    return a;
}
__device__ __forceinline__ void cp_async16(uint32_t s, const void* g) {
    asm volatile("cp.async.cg.shared.global [%0], [%1], 16;" :: "r"(s), "l"(g));
}
__device__ __forceinline__ void cp_commit() { asm volatile("cp.async.commit_group;"); }
template <int N> __device__ __forceinline__ void cp_wait() {
    asm volatile("cp.async.wait_group %0;" :: "n"(N));
}
__device__ __forceinline__ void ldmx4(uint32_t a, uint32_t& d0, uint32_t& d1,
                                      uint32_t& d2, uint32_t& d3) {
    asm volatile("ldmatrix.sync.aligned.m8n8.x4.shared.b16 {%0,%1,%2,%3}, [%4];"
                 : "=r"(d0), "=r"(d1), "=r"(d2), "=r"(d3) : "r"(a));
}
__device__ __forceinline__ void ldmx4t(uint32_t a, uint32_t& d0, uint32_t& d1,
                                       uint32_t& d2, uint32_t& d3) {
    asm volatile("ldmatrix.sync.aligned.m8n8.x4.trans.shared.b16 {%0,%1,%2,%3}, [%4];"
                 : "=r"(d0), "=r"(d1), "=r"(d2), "=r"(d3) : "r"(a));
}
__device__ __forceinline__ void mma_fp16(float* c, const uint32_t* a,
                                         uint32_t b0, uint32_t b1) {
    asm volatile(
        "mma.sync.aligned.m16n8k16.row.col.f32.f16.f16.f32 "
        "{%0,%1,%2,%3}, {%4,%5,%6,%7}, {%8,%9}, {%0,%1,%2,%3};"
        : "+f"(c[0]), "+f"(c[1]), "+f"(c[2]), "+f"(c[3])
        : "r"(a[0]), "r"(a[1]), "r"(a[2]), "r"(a[3]), "r"(b0), "r"(b1));
}
__device__ __forceinline__ uint32_t packh2(float a, float b) {
    __half2 h = __floats2half2_rn(a, b);
    return *(uint32_t*)&h;
}
__device__ __forceinline__ float gelu_t(float x) {
    float x3 = x * x * x;
    float u = 0.7978845608028654f * (x + 0.044715f * x3);
    return 0.5f * x * (1.0f + tanhf(u));
}

// ---------------------------------------------------------------------------
// RoPE table init (one block, 512 threads)
// ---------------------------------------------------------------------------
__global__ void rope_tab_k() {
    int i = threadIdx.x;            // 0..511
    int pos = i >> 4, t = i & 15;
    float inv = powf(10000.0f, -(float)t * (1.0f / 16.0f));
    float s, c;
    sincosf((float)pos * inv, &s, &c);
    g_ropetab[i] = make_float2(c, s);
}

// ---------------------------------------------------------------------------
// fp32 -> fp16 convert, float4-vectorized
// ---------------------------------------------------------------------------
__global__ void cvt_h_k(const float4* __restrict__ in, __half2* __restrict__ o, int n4) {
    int i = blockIdx.x * 256 + threadIdx.x;
    if (i >= n4) return;
    float4 v = in[i];
    o[2 * i]     = __floats2half2_rn(v.x, v.y);
    o[2 * i + 1] = __floats2half2_rn(v.z, v.w);
}

// ---------------------------------------------------------------------------
// Patch gather
// ---------------------------------------------------------------------------
__global__ void patch_gather_k(const float* __restrict__ x, float* __restrict__ patch) {
    int idx = blockIdx.x * 256 + threadIdx.x;
    if (idx >= TOK * 64) return;
    int k = idx & 63, t = idx >> 6;
    int n = t >> 10, l = t & (L - 1);
    int hf = l >> 5, wf = l & 31;
    int c = k >> 2, kh = (k >> 1) & 1, kw = k & 1;
    patch[idx] = x[((n * CIN + c) * HIN + (hf * 2 + kh)) * WIN + (wf * 2 + kw)];
}

// ---------------------------------------------------------------------------
// RMSNorm
// ---------------------------------------------------------------------------
__device__ __forceinline__ float rms_row_scale(const float4 v, int tid) {
    float ss = v.x * v.x + v.y * v.y + v.z * v.z + v.w * v.w;
    #pragma unroll
    for (int o = 16; o; o >>= 1) ss += __shfl_xor_sync(0xffffffffu, ss, o);
    __shared__ float ws[8];
    if ((tid & 31) == 0) ws[tid >> 5] = ss;
    __syncthreads();
    float tot = 0.f;
    #pragma unroll
    for (int i = 0; i < 8; i++) tot += ws[i];
    return rsqrtf(tot * (1.0f / (float)D) + 1e-6f);
}

__global__ __launch_bounds__(256) void rmsnorm_k(const float* __restrict__ in,
                                                 float* __restrict__ out) {
    int row = blockIdx.x;
    float4 v = ((const float4*)(in + (size_t)row * D))[threadIdx.x];
    float r = rms_row_scale(v, threadIdx.x);
    ((float4*)(out + (size_t)row * D))[threadIdx.x] =
        make_float4(v.x * r, v.y * r, v.z * r, v.w * r);
}

__global__ __launch_bounds__(256) void rmsnorm_h_k(const float* __restrict__ in,
                                                   __half* __restrict__ out) {
    int row = blockIdx.x;
    float4 v = ((const float4*)(in + (size_t)row * D))[threadIdx.x];
    float r = rms_row_scale(v, threadIdx.x);
    size_t base = (size_t)row * D + threadIdx.x * 4;
    *(__half2*)(out + base)     = __floats2half2_rn(v.x * r, v.y * r);
    *(__half2*)(out + base + 2) = __floats2half2_rn(v.z * r, v.w * r);
}

// ---------------------------------------------------------------------------
// fp16 tensor-core GEMM (R12-proven config): C = A[M,K] @ W[N,K]^T
// BM=128, BN=128, BK=32, 256 thr, 8 warps (32x64), 2 CTAs/SM,
// 3-stage cp.async pipeline, 80B padded smem rows, two barriers/iter.
// MODE 1: fp16 = gelu(acc+bias). MODE 2: fp32 = res+acc+bias.
// MODE 3: fp16 qkv with fused RoPE (q scaled 1/8, q/k rotated, v converted).
// ---------------------------------------------------------------------------
#define BM 128
#define BN 128
#define BK 32
#define PADK 40
#define ROWB (PADK * 2)                 // 80 bytes
#define MATB (BM * ROWB)                // 10240 B per matrix
#define STGB (2 * MATB)                 // 20480 B per stage (A, W)
#define NSTG 3
#define GSMEM (NSTG * STGB)             // 61440 B -> 2 CTAs/SM

__device__ __forceinline__ void g_load_stage(
    uint32_t sb, const __half* __restrict__ A, const __half* __restrict__ B,
    int m0, int n0, int K, int k0, int tid)
{
    #pragma unroll
    for (int i = tid; i < 512; i += 256) {
        int r = i >> 2, c = i & 3;
        uint32_t off = (uint32_t)r * ROWB + (uint32_t)c * 16;
        size_t ga = (size_t)(m0 + r) * K + k0 + c * 8;
        size_t gb = (size_t)(n0 + r) * K + k0 + c * 8;
        cp_async16(sb + off,        A + ga);
        cp_async16(sb + MATB + off, B + gb);
    }
    cp_commit();
}

template <int MODE>
__global__ __launch_bounds__(256, 2)
void hgemm_k(const __half* __restrict__ A, const __half* __restrict__ W,
             const float* __restrict__ bias, const float* res,
             float* Cf, __half* Ch, int N, int K)
{
    extern __shared__ char dsm[];
    uint32_t sbase = smem_u32(dsm);
    int tid = threadIdx.x, lane = tid & 31, warp = tid >> 5;
    int m0 = blockIdx.y * BM, n0 = blockIdx.x * BN;
    int warp_m = (warp & 3) * 32;
    int warp_n = (warp >> 2) * 64;

    float acc[2][8][4];
    #pragma unroll
    for (int a = 0; a < 2; a++)
        #pragma unroll
        for (int b = 0; b < 8; b++)
            #pragma unroll
            for (int c = 0; c < 4; c++) acc[a][b][c] = 0.f;

    int NC = K / BK;                     // >= 32
    g_load_stage(sbase,            A, W, m0, n0, K, 0,      tid);
    g_load_stage(sbase + STGB,     A, W, m0, n0, K, BK,     tid);
    g_load_stage(sbase + 2 * STGB, A, W, m0, n0, K, 2 * BK, tid);

    uint32_t a_row = (uint32_t)(warp_m + (lane & 15));
    uint32_t a_koff = (uint32_t)(lane >> 4) * 16;

    int slot = 0;
    for (int it = 0; it < NC; it++) {
        uint32_t sb = sbase + (uint32_t)slot * STGB;
        if (it + 3 <= NC)      cp_wait<2>();
        else if (it + 2 == NC) cp_wait<1>();
        else                   cp_wait<0>();
        __syncthreads();

        #pragma unroll
        for (int k16 = 0; k16 < 2; k16++) {
            uint32_t kb = (uint32_t)k16 * 32 + a_koff;
            uint32_t ah[2][4];
            #pragma unroll
            for (int mf = 0; mf < 2; mf++) {
                uint32_t ra = sb + (a_row + mf * 16) * ROWB + kb;
                ldmx4(ra, ah[mf][0], ah[mf][1], ah[mf][2], ah[mf][3]);
            }
            #pragma unroll
            for (int nh = 0; nh < 2; nh++) {
                #pragma unroll
                for (int pr = 0; pr < 2; pr++) {
                    uint32_t nrow = (uint32_t)(warp_n + nh * 32 + pr * 16 + (lane & 15));
                    uint32_t rb = sb + MATB + nrow * ROWB + kb;
                    uint32_t b0, b1, b2, b3;
                    ldmx4(rb, b0, b1, b2, b3);
                    #pragma unroll
                    for (int mf = 0; mf < 2; mf++) {
                        mma_fp16(acc[mf][nh * 4 + pr * 2],     ah[mf], b0, b2);
                        mma_fp16(acc[mf][nh * 4 + pr * 2 + 1], ah[mf], b1, b3);
                    }
                }
            }
        }
        __syncthreads();
        if (it + 3 < NC)
            g_load_stage(sb, A, W, m0, n0, K, (it + 3) * BK, tid);
        slot = (slot == NSTG - 1) ? 0 : slot + 1;
    }

    int r0 = m0 + warp_m + (lane >> 2);

    if (MODE == 3) {
        int sec0 = n0 + warp_n;              // warp-uniform section base (mult of 64)
        if (sec0 >= 2 * D) {
            // ---- v section: bias + fp16 convert ----
            #pragma unroll
            for (int mf = 0; mf < 2; mf++) {
                #pragma unroll
                for (int nf = 0; nf < 8; nf++) {
                    int col = sec0 + nf * 8 + (lane & 3) * 2;
                    float bx = __ldg(bias + col), by = __ldg(bias + col + 1);
                    #pragma unroll
                    for (int half = 0; half < 2; half++) {
                        int row = r0 + mf * 16 + half * 8;
                        float v0 = acc[mf][nf][half * 2]     + bx;
                        float v1 = acc[mf][nf][half * 2 + 1] + by;
                        *(__half2*)(Ch + (size_t)row * N + col) = __floats2half2_rn(v0, v1);
                    }
                }
            }
        } else {
            // ---- q/k section: bias + RoPE (+1/8 scale for q) + fp16 ----
            const float qs = (sec0 < D) ? 0.125f : 1.0f;
            #pragma unroll
            for (int mf = 0; mf < 2; mf++) {
                #pragma unroll
                for (int half = 0; half < 2; half++) {
                    int row = r0 + mf * 16 + half * 8;
                    int l = row & (L - 1);
                    int ph = l >> 5, pw = l & 31;
                    #pragma unroll
                    for (int g = 0; g < 4; g++) {
                        int nfp = (g & 1) | ((g >> 1) * 4);    // 0,1,4,5
                        int pos = (nfp < 4) ? ph : pw;
                        int colA = sec0 + nfp * 8 + (lane & 3) * 2;
                        int colB = colA + 16;
                        float y0[2], y1[2];
                        #pragma unroll
                        for (int cc = 0; cc < 2; cc++) {
                            int t = (nfp & 3) * 8 + (lane & 3) * 2 + cc;
                            float2 cs = g_ropetab[pos * 16 + t];
                            float x0 = acc[mf][nfp][half * 2 + cc]     + __ldg(bias + colA + cc);
                            float x1 = acc[mf][nfp + 2][half * 2 + cc] + __ldg(bias + colB + cc);
                            y0[cc] = (x0 * cs.x - x1 * cs.y) * qs;
                            y1[cc] = (x1 * cs.x + x0 * cs.y) * qs;
                        }
                        size_t rb = (size_t)row * N;
                        *(__half2*)(Ch + rb + colA) = __floats2half2_rn(y0[0], y0[1]);
                        *(__half2*)(Ch + rb + colB) = __floats2half2_rn(y1[0], y1[1]);
                    }
                }
            }
        }
        return;
    }

    #pragma unroll
    for (int mf = 0; mf < 2; mf++) {
        #pragma unroll
        for (int nf = 0; nf < 8; nf++) {
            int col = n0 + warp_n + nf * 8 + (lane & 3) * 2;
            float bx = __ldg(bias + col), by = __ldg(bias + col + 1);
            #pragma unroll
            for (int half = 0; half < 2; half++) {
                int row = r0 + mf * 16 + half * 8;
                float v0 = acc[mf][nf][half * 2]     + bx;
                float v1 = acc[mf][nf][half * 2 + 1] + by;
                size_t base = (size_t)row * N + col;
                if (MODE == 1) {
                    v0 = gelu_t(v0); v1 = gelu_t(v1);
                    *(__half2*)(Ch + base) = __floats2half2_rn(v0, v1);
                } else {
                    if (MODE == 2) {
                        float2 rr = *(const float2*)(res + base);
                        v0 += rr.x; v1 += rr.y;
                    }
                    *(float2*)(Cf + base) = make_float2(v0, v1);
                }
            }
        }
    }
}

// ---------------------------------------------------------------------------
// fp32 SGEMM for the tiny merge GEMM (K=64)
// ---------------------------------------------------------------------------
__global__ __launch_bounds__(256) void sgemm_k(
    const float* __restrict__ A, const float* __restrict__ W,
    float* __restrict__ C, int M, int N, int K) {
    __shared__ float As[16][64];
    __shared__ float Bs[16][64];
    int tid = threadIdx.x;
    int m0 = blockIdx.y * 64, n0 = blockIdx.x * 64;
    int tx = tid & 15, ty = tid >> 4;
    int lr = tid >> 2;
    int lk = (tid & 3) * 4;
    const float* Ap = A + (size_t)(m0 + lr) * K + lk;
    const float* Wp = W + (size_t)(n0 + lr) * K + lk;
    float acc[4][4];
    #pragma unroll
    for (int i = 0; i < 4; i++)
        #pragma unroll
        for (int j = 0; j < 4; j++) acc[i][j] = 0.f;
    for (int k0 = 0; k0 < K; k0 += 16) {
        float4 av = *(const float4*)(Ap + k0);
        float4 bv = *(const float4*)(Wp + k0);
        As[lk + 0][lr] = av.x; As[lk + 1][lr] = av.y;
        As[lk + 2][lr] = av.z; As[lk + 3][lr] = av.w;
        Bs[lk + 0][lr] = bv.x; Bs[lk + 1][lr] = bv.y;
        Bs[lk + 2][lr] = bv.z; Bs[lk + 3][lr] = bv.w;
        __syncthreads();
        #pragma unroll
        for (int k = 0; k < 16; k++) {
            float4 a = *(const float4*)&As[k][ty * 4];
            float4 b = *(const float4*)&Bs[k][tx * 4];
            acc[0][0] += a.x * b.x; acc[0][1] += a.x * b.y; acc[0][2] += a.x * b.z; acc[0][3] += a.x * b.w;
            acc[1][0] += a.y * b.x; acc[1][1] += a.y * b.y; acc[1][2] += a.y * b.z; acc[1][3] += a.y * b.w;
            acc[2][0] += a.z * b.x; acc[2][1] += a.z * b.y; acc[2][2] += a.z * b.z; acc[2][3] += a.z * b.w;
            acc[3][0] += a.w * b.x; acc[3][1] += a.w * b.y; acc[3][2] += a.w * b.z; acc[3][3] += a.w * b.w;
        }
        __syncthreads();
    }
    #pragma unroll
    for (int i = 0; i < 4; i++) {
        int m = m0 + ty * 4 + i;
        *(float4*)(C + (size_t)m * N + n0 + tx * 4) =
            make_float4(acc[i][0], acc[i][1], acc[i][2], acc[i][3]);
    }
}

// ---------------------------------------------------------------------------
// HMMA flash attention (fp16 inputs, fp32 accum) -> fp16 output.
// ---------------------------------------------------------------------------
#define APADB 144
#define AQ_B  (128 * APADB)
#define AKV_B (64 * APADB)
#define ASTG_B (2 * AKV_B)
#define ATT_SMEM (AQ_B + 2 * ASTG_B)

__global__ __launch_bounds__(256) void attn_mma_k(const __half* __restrict__ qkvh,
                                                  __half* __restrict__ oh) {
    extern __shared__ char attsm[];
    uint32_t sb0 = smem_u32(attsm);
    int tid = threadIdx.x, lane = tid & 31, warp = tid >> 5;
    int h = blockIdx.y, n = blockIdx.z;
    int q0 = blockIdx.x * 128;

    const __half* qbase = qkvh + ((size_t)(n * L + q0)) * D3 + h * DH;
    const __half* kbase = qkvh + (size_t)n * L * D3 + D + h * DH;
    const __half* vbase = kbase + D;

    for (int i = tid; i < 1024; i += 256) {
        int r = i >> 3, g = i & 7;
        cp_async16(sb0 + (uint32_t)r * APADB + g * 16, qbase + (size_t)r * D3 + g * 8);
    }
    cp_commit();

    auto load_kv = [&](int t) {
        uint32_t s = sb0 + AQ_B + (uint32_t)(t & 1) * ASTG_B;
        const __half* kb = kbase + (size_t)(t * 64) * D3;
        const __half* vb = vbase + (size_t)(t * 64) * D3;
        for (int i = tid; i < 512; i += 256) {
            int r = i >> 3, g = i & 7;
            uint32_t off = (uint32_t)r * APADB + g * 16;
            cp_async16(s + off,         kb + (size_t)r * D3 + g * 8);
            cp_async16(s + AKV_B + off, vb + (size_t)r * D3 + g * 8);
        }
        cp_commit();
    };
    load_kv(0);
    load_kv(1);
    cp_wait<2>();
    __syncthreads();

    uint32_t qf[4][4];
    {
        uint32_t qrow = (uint32_t)(warp * 16 + (lane & 15));
        uint32_t kseg = (uint32_t)(lane >> 4) * 16;
        #pragma unroll
        for (int ks = 0; ks < 4; ks++)
            ldmx4(sb0 + qrow * APADB + kseg + ks * 32,
                  qf[ks][0], qf[ks][1], qf[ks][2], qf[ks][3]);
    }

    float m0 = -1e30f, m1 = -1e30f, l0 = 0.f, l1 = 0.f;
    float oacc[8][4];
    #pragma unroll
    for (int f = 0; f < 8; f++)
        #pragma unroll
        for (int c = 0; c < 4; c++) oacc[f][c] = 0.f;

    for (int t = 0; t < 16; t++) {
        uint32_t s = sb0 + AQ_B + (uint32_t)(t & 1) * ASTG_B;
        if (t + 1 < 16) cp_wait<1>(); else cp_wait<0>();
        __syncthreads();

        float sc[8][4];
        #pragma unroll
        for (int f = 0; f < 8; f++)
            #pragma unroll
            for (int c = 0; c < 4; c++) sc[f][c] = 0.f;

        #pragma unroll
        for (int ks = 0; ks < 4; ks++) {
            #pragma unroll
            for (int sg = 0; sg < 4; sg++) {
                uint32_t addr = s + (uint32_t)(sg * 16 + (lane & 15)) * APADB +
                                (uint32_t)(lane >> 4) * 16 + ks * 32;
                uint32_t b0, b1, b2, b3;
                ldmx4(addr, b0, b1, b2, b3);
                mma_fp16(sc[sg * 2],     qf[ks], b0, b2);
                mma_fp16(sc[sg * 2 + 1], qf[ks], b1, b3);
            }
        }

        float rmax0 = -1e30f, rmax1 = -1e30f;
        #pragma unroll
        for (int f = 0; f < 8; f++) {
            rmax0 = fmaxf(rmax0, fmaxf(sc[f][0], sc[f][1]));
            rmax1 = fmaxf(rmax1, fmaxf(sc[f][2], sc[f][3]));
        }
        rmax0 = fmaxf(rmax0, __shfl_xor_sync(0xffffffffu, rmax0, 1));
        rmax0 = fmaxf(rmax0, __shfl_xor_sync(0xffffffffu, rmax0, 2));
        rmax1 = fmaxf(rmax1, __shfl_xor_sync(0xffffffffu, rmax1, 1));
        rmax1 = fmaxf(rmax1, __shfl_xor_sync(0xffffffffu, rmax1, 2));
        float mn0 = fmaxf(m0, rmax0), mn1 = fmaxf(m1, rmax1);
        float sf0 = __expf(m0 - mn0), sf1 = __expf(m1 - mn1);
        m0 = mn0; m1 = mn1;
        l0 *= sf0; l1 *= sf1;
        #pragma unroll
        for (int f = 0; f < 8; f++) {
            oacc[f][0] *= sf0; oacc[f][1] *= sf0;
            oacc[f][2] *= sf1; oacc[f][3] *= sf1;
        }
        float rs0 = 0.f, rs1 = 0.f;
        #pragma unroll
        for (int f = 0; f < 8; f++) {
            sc[f][0] = __expf(sc[f][0] - m0);
            sc[f][1] = __expf(sc[f][1] - m0);
            sc[f][2] = __expf(sc[f][2] - m1);
            sc[f][3] = __expf(sc[f][3] - m1);
            rs0 += sc[f][0] + sc[f][1];
            rs1 += sc[f][2] + sc[f][3];
        }
        rs0 += __shfl_xor_sync(0xffffffffu, rs0, 1);
        rs0 += __shfl_xor_sync(0xffffffffu, rs0, 2);
        rs1 += __shfl_xor_sync(0xffffffffu, rs1, 1);
        rs1 += __shfl_xor_sync(0xffffffffu, rs1, 2);
        l0 += rs0; l1 += rs1;

        uint32_t pa[4][4];
        #pragma unroll
        for (int j = 0; j < 4; j++) {
            pa[j][0] = packh2(sc[2 * j][0],     sc[2 * j][1]);
            pa[j][1] = packh2(sc[2 * j][2],     sc[2 * j][3]);
            pa[j][2] = packh2(sc[2 * j + 1][0], sc[2 * j + 1][1]);
            pa[j][3] = packh2(sc[2 * j + 1][2], sc[2 * j + 1][3]);
        }

        uint32_t vb = s + AKV_B;
        #pragma unroll
        for (int j = 0; j < 4; j++) {
            #pragma unroll
            for (int dseg = 0; dseg < 4; dseg++) {
                uint32_t addr = vb + (uint32_t)(j * 16 + (lane & 15)) * APADB +
                                (uint32_t)(lane >> 4) * 16 + dseg * 32;
                uint32_t b0, b1, b2, b3;
                ldmx4t(addr, b0, b1, b2, b3);
                mma_fp16(oacc[dseg * 2],     pa[j], b0, b1);
                mma_fp16(oacc[dseg * 2 + 1], pa[j], b2, b3);
            }
        }
        __syncthreads();
        if (t + 2 < 16) load_kv(t + 2);
    }

    float inv0 = 1.0f / l0, inv1 = 1.0f / l1;
    int row0 = q0 + warp * 16 + (lane >> 2);
    #pragma unroll
    for (int f = 0; f < 8; f++) {
        int col = h * DH + f * 8 + (lane & 3) * 2;
        #pragma unroll
        for (int half = 0; half < 2; half++) {
            int row = row0 + half * 8;
            float v0 = oacc[f][half * 2]     * (half ? inv1 : inv0);
            float v1 = oacc[f][half * 2 + 1] * (half ? inv1 : inv0);
            size_t base = ((size_t)(n * L + row)) * D + col;
            *(__half2*)(oh + base) = __floats2half2_rn(v0, v1);
        }
    }
}

// ---------------------------------------------------------------------------
// Transpose [N, L, D] -> [N, D, L]
// ---------------------------------------------------------------------------
__global__ void transpose_k(const float* __restrict__ in, float* __restrict__ out) {
    __shared__ float tile[32][33];
    int n = blockIdx.z;
    int l0 = blockIdx.x * 32, d0 = blockIdx.y * 32;
    int tx = threadIdx.x, ty = threadIdx.y;
    #pragma unroll
    for (int i = ty; i < 32; i += 8)
        tile[i][tx] = in[((size_t)(n * L + l0 + i)) * D + d0 + tx];
    __syncthreads();
    #pragma unroll
    for (int i = ty; i < 32; i += 8)
        out[((size_t)(n * D + d0 + i)) * L + l0 + tx] = tile[tx][i];
}

// ---------------------------------------------------------------------------
// Launch
// ---------------------------------------------------------------------------
extern "C" void kernel_launch(void* const* d_in, const int* in_sizes, int n_in,
                              void* d_out, int out_size) {
    const float* x       = (const float*)d_in[0];
    const float* merge_w = (const float*)d_in[1];
    const float* qkv_w   = (const float*)d_in[2];
    const float* qkv_b   = (const float*)d_in[3];
    const float* proj_w  = (const float*)d_in[4];
    const float* proj_b  = (const float*)d_in[5];
    const float* fc1_w   = (const float*)d_in[6];
    const float* fc1_b   = (const float*)d_in[7];
    const float* fc2_w   = (const float*)d_in[8];
    const float* fc2_b   = (const float*)d_in[9];
    float* out = (float*)d_out;

    float *patch, *tok, *hbuf;
    __half *qkvh, *h_h, *att_h, *mlp_h;
    __half *wqkv_h, *wproj_h, *wfc1_h, *wfc2_h;
    cudaGetSymbolAddress((void**)&patch,  g_patch);
    cudaGetSymbolAddress((void**)&tok,    g_tok);
    cudaGetSymbolAddress((void**)&hbuf,   g_h);
    cudaGetSymbolAddress((void**)&qkvh,   g_qkvh);
    cudaGetSymbolAddress((void**)&h_h,    g_h_h);
    cudaGetSymbolAddress((void**)&att_h,  g_att_h);
    cudaGetSymbolAddress((void**)&mlp_h,  g_mlp_h);
    cudaGetSymbolAddress((void**)&wqkv_h, g_wqkv_h);
    cudaGetSymbolAddress((void**)&wproj_h, g_wproj_h);
    cudaGetSymbolAddress((void**)&wfc1_h, g_wfc1_h);
    cudaGetSymbolAddress((void**)&wfc2_h, g_wfc2_h);

    cudaFuncSetAttribute(hgemm_k<1>, cudaFuncAttributeMaxDynamicSharedMemorySize, GSMEM);
    cudaFuncSetAttribute(hgemm_k<2>, cudaFuncAttributeMaxDynamicSharedMemorySize, GSMEM);
    cudaFuncSetAttribute(hgemm_k<3>, cudaFuncAttributeMaxDynamicSharedMemorySize, GSMEM);
    cudaFuncSetAttribute(attn_mma_k, cudaFuncAttributeMaxDynamicSharedMemorySize, ATT_SMEM);

    rope_tab_k<<<1, 512>>>();

    // Convert weights to fp16
    cvt_h_k<<<(DEPTH * D3 * D / 4 + 255) / 256, 256>>>(
        (const float4*)qkv_w, (__half2*)wqkv_h, DEPTH * D3 * D / 4);
    cvt_h_k<<<(DEPTH * D * D / 4 + 255) / 256, 256>>>(
        (const float4*)proj_w, (__half2*)wproj_h, DEPTH * D * D / 4);
    cvt_h_k<<<(DEPTH * D4 * D / 4 + 255) / 256, 256>>>(
        (const float4*)fc1_w, (__half2*)wfc1_h, DEPTH * D4 * D / 4);
    cvt_h_k<<<(DEPTH * D * D4 / 4 + 255) / 256, 256>>>(
        (const float4*)fc2_w, (__half2*)wfc2_h, DEPTH * D * D4 / 4);

    patch_gather_k<<<(TOK * 64 + 255) / 256, 256>>>(x, patch);
    sgemm_k<<<dim3(D / 64, TOK / 64), 256>>>(patch, merge_w, tok, TOK, D, 64);

    for (int i = 0; i < DEPTH; i++) {
        // attention block: QKV GEMM with fused RoPE+fp16 epilogue
        rmsnorm_h_k<<<TOK, 256>>>(tok, h_h);
        hgemm_k<3><<<dim3(D3 / BN, TOK / BM), 256, GSMEM>>>(
            h_h, wqkv_h + (size_t)i * D3 * D,
            qkv_b + (size_t)i * D3, nullptr, nullptr, qkvh, D3, D);
        attn_mma_k<<<dim3(L / 128, HEADS, NB), 256, ATT_SMEM>>>(qkvh, att_h);
        hgemm_k<2><<<dim3(D / BN, TOK / BM), 256, GSMEM>>>(
            att_h, wproj_h + (size_t)i * D * D,
            proj_b + (size_t)i * D, tok, tok, nullptr, D, D);
        // MLP block
        rmsnorm_h_k<<<TOK, 256>>>(tok, h_h);
        hgemm_k<1><<<dim3(D4 / BN, TOK / BM), 256, GSMEM>>>(
            h_h, wfc1_h + (size_t)i * D4 * D,
            fc1_b + (size_t)i * D4, nullptr, nullptr, mlp_h, D4, D);
        hgemm_k<2><<<dim3(D / BN, TOK / BM), 256, GSMEM>>>(
            mlp_h, wfc2_h + (size_t)i * D * D4,
            fc2_b + (size_t)i * D, tok, tok, nullptr, D, D4);
    }

    rmsnorm_k<<<TOK, 256>>>(tok, hbuf);
    transpose_k<<<dim3(L / 32, D / 32, NB), dim3(32, 8)>>>(hbuf, out);
}

// round 15
// speedup vs baseline: 1.5003x; 1.5003x over previous
#include <cuda_runtime.h>
#include <cuda_bf16.h>
#include <cuda_fp16.h>
#include <cstdint>
#include <cstdio>

// ---------------------------------------------------------------------------
// Problem constants
// ---------------------------------------------------------------------------
#define NB    4
#define CIN   16
#define HIN   64
#define WIN   64
#define HF    32
#define WF    32
#define L     1024
#define D     1024
#define HEADS 16
#define DH    64
#define DEPTH 8
#define TOK   (NB*L)       // 4096
#define D3    (3*D)        // 3072
#define D4    (4*D)        // 4096

// ---------------------------------------------------------------------------
// Scratch (static device globals; no runtime allocation)
// ---------------------------------------------------------------------------
__device__ float g_patch[TOK * 64];
__device__ float g_tok  [TOK * D];
__device__ float g_h    [TOK * D];
__device__ __half g_qkvh[TOK * D3];

__device__ __half g_h_h  [TOK * D];     // fp16 rmsnorm output (GEMM A)
__device__ __half g_att_h[TOK * D];     // fp16 attention output
__device__ __half g_mlp_h[TOK * D4];    // fp16 gelu(fc1) output

// fp16 weights (all depths)
__device__ __half g_wqkv_h[DEPTH * D3 * D];
__device__ __half g_wproj_h[DEPTH * D * D];
__device__ __half g_wfc1_h[DEPTH * D4 * D];
__device__ __half g_wfc2_h[DEPTH * D * D4];

// ---------------------------------------------------------------------------
// Helpers
// ---------------------------------------------------------------------------
__device__ __forceinline__ uint32_t smem_u32(const void* p) {
    uint32_t a;
    asm("{ .reg .u64 t; cvta.to.shared.u64 t, %1; cvt.u32.u64 %0, t; }" : "=r"(a) : "l"(p));
    return a;
}
__device__ __forceinline__ void cp_async16(uint32_t s, const void* g) {
    asm volatile("cp.async.cg.shared.global [%0], [%1], 16;" :: "r"(s), "l"(g));
}
__device__ __forceinline__ void cp_commit() { asm volatile("cp.async.commit_group;"); }
template <int N> __device__ __forceinline__ void cp_wait() {
    asm volatile("cp.async.wait_group %0;" :: "n"(N));
}
__device__ __forceinline__ void ldmx4(uint32_t a, uint32_t& d0, uint32_t& d1,
                                      uint32_t& d2, uint32_t& d3) {
    asm volatile("ldmatrix.sync.aligned.m8n8.x4.shared.b16 {%0,%1,%2,%3}, [%4];"
                 : "=r"(d0), "=r"(d1), "=r"(d2), "=r"(d3) : "r"(a));
}
__device__ __forceinline__ void ldmx4t(uint32_t a, uint32_t& d0, uint32_t& d1,
                                       uint32_t& d2, uint32_t& d3) {
    asm volatile("ldmatrix.sync.aligned.m8n8.x4.trans.shared.b16 {%0,%1,%2,%3}, [%4];"
                 : "=r"(d0), "=r"(d1), "=r"(d2), "=r"(d3) : "r"(a));
}
__device__ __forceinline__ void mma_fp16(float* c, const uint32_t* a,
                                         uint32_t b0, uint32_t b1) {
    asm volatile(
        "mma.sync.aligned.m16n8k16.row.col.f32.f16.f16.f32 "
        "{%0,%1,%2,%3}, {%4,%5,%6,%7}, {%8,%9}, {%0,%1,%2,%3};"
        : "+f"(c[0]), "+f"(c[1]), "+f"(c[2]), "+f"(c[3])
        : "r"(a[0]), "r"(a[1]), "r"(a[2]), "r"(a[3]), "r"(b0), "r"(b1));
}
__device__ __forceinline__ uint32_t packh2(float a, float b) {
    __half2 h = __floats2half2_rn(a, b);
    return *(uint32_t*)&h;
}
__device__ __forceinline__ float gelu_t(float x) {
    float x3 = x * x * x;
    float u = 0.7978845608028654f * (x + 0.044715f * x3);
    return 0.5f * x * (1.0f + tanhf(u));
}

// ---------------------------------------------------------------------------
// fp32 -> fp16 convert, float4-vectorized
// ---------------------------------------------------------------------------
__global__ void cvt_h_k(const float4* __restrict__ in, __half2* __restrict__ o, int n4) {
    int i = blockIdx.x * 256 + threadIdx.x;
    if (i >= n4) return;
    float4 v = in[i];
    o[2 * i]     = __floats2half2_rn(v.x, v.y);
    o[2 * i + 1] = __floats2half2_rn(v.z, v.w);
}

// ---------------------------------------------------------------------------
// Patch gather
// ---------------------------------------------------------------------------
__global__ void patch_gather_k(const float* __restrict__ x, float* __restrict__ patch) {
    int idx = blockIdx.x * 256 + threadIdx.x;
    if (idx >= TOK * 64) return;
    int k = idx & 63, t = idx >> 6;
    int n = t >> 10, l = t & (L - 1);
    int hf = l >> 5, wf = l & 31;
    int c = k >> 2, kh = (k >> 1) & 1, kw = k & 1;
    patch[idx] = x[((n * CIN + c) * HIN + (hf * 2 + kh)) * WIN + (wf * 2 + kw)];
}

// ---------------------------------------------------------------------------
// RMSNorm
// ---------------------------------------------------------------------------
__device__ __forceinline__ float rms_row_scale(const float4 v, int tid) {
    float ss = v.x * v.x + v.y * v.y + v.z * v.z + v.w * v.w;
    #pragma unroll
    for (int o = 16; o; o >>= 1) ss += __shfl_xor_sync(0xffffffffu, ss, o);
    __shared__ float ws[8];
    if ((tid & 31) == 0) ws[tid >> 5] = ss;
    __syncthreads();
    float tot = 0.f;
    #pragma unroll
    for (int i = 0; i < 8; i++) tot += ws[i];
    return rsqrtf(tot * (1.0f / (float)D) + 1e-6f);
}

__global__ __launch_bounds__(256) void rmsnorm_k(const float* __restrict__ in,
                                                 float* __restrict__ out) {
    int row = blockIdx.x;
    float4 v = ((const float4*)(in + (size_t)row * D))[threadIdx.x];
    float r = rms_row_scale(v, threadIdx.x);
    ((float4*)(out + (size_t)row * D))[threadIdx.x] =
        make_float4(v.x * r, v.y * r, v.z * r, v.w * r);
}

__global__ __launch_bounds__(256) void rmsnorm_h_k(const float* __restrict__ in,
                                                   __half* __restrict__ out) {
    int row = blockIdx.x;
    float4 v = ((const float4*)(in + (size_t)row * D))[threadIdx.x];
    float r = rms_row_scale(v, threadIdx.x);
    size_t base = (size_t)row * D + threadIdx.x * 4;
    *(__half2*)(out + base)     = __floats2half2_rn(v.x * r, v.y * r);
    *(__half2*)(out + base + 2) = __floats2half2_rn(v.z * r, v.w * r);
}

// ---------------------------------------------------------------------------
// fp16 tensor-core GEMM (R12-proven config): C = A[M,K] @ W[N,K]^T
// BM=128, BN=128, BK=32, 256 thr, 8 warps (32x64), 2 CTAs/SM,
// 3-stage cp.async pipeline, 80B padded smem rows, two barriers/iter.
// MODE 1: fp16 = gelu(acc+bias). MODE 2: fp32 = res+acc+bias.
// MODE 4: fp16 = acc+bias (QKV; rope applied by separate in-place kernel).
// ---------------------------------------------------------------------------
#define BM 128
#define BN 128
#define BK 32
#define PADK 40
#define ROWB (PADK * 2)                 // 80 bytes
#define MATB (BM * ROWB)                // 10240 B per matrix
#define STGB (2 * MATB)                 // 20480 B per stage (A, W)
#define NSTG 3
#define GSMEM (NSTG * STGB)             // 61440 B -> 2 CTAs/SM

__device__ __forceinline__ void g_load_stage(
    uint32_t sb, const __half* __restrict__ A, const __half* __restrict__ B,
    int m0, int n0, int K, int k0, int tid)
{
    #pragma unroll
    for (int i = tid; i < 512; i += 256) {
        int r = i >> 2, c = i & 3;
        uint32_t off = (uint32_t)r * ROWB + (uint32_t)c * 16;
        size_t ga = (size_t)(m0 + r) * K + k0 + c * 8;
        size_t gb = (size_t)(n0 + r) * K + k0 + c * 8;
        cp_async16(sb + off,        A + ga);
        cp_async16(sb + MATB + off, B + gb);
    }
    cp_commit();
}

template <int MODE>
__global__ __launch_bounds__(256, 2)
void hgemm_k(const __half* __restrict__ A, const __half* __restrict__ W,
             const float* __restrict__ bias, const float* res,
             float* Cf, __half* Ch, int N, int K)
{
    extern __shared__ char dsm[];
    uint32_t sbase = smem_u32(dsm);
    int tid = threadIdx.x, lane = tid & 31, warp = tid >> 5;
    int m0 = blockIdx.y * BM, n0 = blockIdx.x * BN;
    int warp_m = (warp & 3) * 32;
    int warp_n = (warp >> 2) * 64;

    float acc[2][8][4];
    #pragma unroll
    for (int a = 0; a < 2; a++)
        #pragma unroll
        for (int b = 0; b < 8; b++)
            #pragma unroll
            for (int c = 0; c < 4; c++) acc[a][b][c] = 0.f;

    int NC = K / BK;                     // >= 32
    g_load_stage(sbase,            A, W, m0, n0, K, 0,      tid);
    g_load_stage(sbase + STGB,     A, W, m0, n0, K, BK,     tid);
    g_load_stage(sbase + 2 * STGB, A, W, m0, n0, K, 2 * BK, tid);

    uint32_t a_row = (uint32_t)(warp_m + (lane & 15));
    uint32_t a_koff = (uint32_t)(lane >> 4) * 16;

    int slot = 0;
    for (int it = 0; it < NC; it++) {
        uint32_t sb = sbase + (uint32_t)slot * STGB;
        if (it + 3 <= NC)      cp_wait<2>();
        else if (it + 2 == NC) cp_wait<1>();
        else                   cp_wait<0>();
        __syncthreads();

        #pragma unroll
        for (int k16 = 0; k16 < 2; k16++) {
            uint32_t kb = (uint32_t)k16 * 32 + a_koff;
            uint32_t ah[2][4];
            #pragma unroll
            for (int mf = 0; mf < 2; mf++) {
                uint32_t ra = sb + (a_row + mf * 16) * ROWB + kb;
                ldmx4(ra, ah[mf][0], ah[mf][1], ah[mf][2], ah[mf][3]);
            }
            #pragma unroll
            for (int nh = 0; nh < 2; nh++) {
                #pragma unroll
                for (int pr = 0; pr < 2; pr++) {
                    uint32_t nrow = (uint32_t)(warp_n + nh * 32 + pr * 16 + (lane & 15));
                    uint32_t rb = sb + MATB + nrow * ROWB + kb;
                    uint32_t b0, b1, b2, b3;
                    ldmx4(rb, b0, b1, b2, b3);
                    #pragma unroll
                    for (int mf = 0; mf < 2; mf++) {
                        mma_fp16(acc[mf][nh * 4 + pr * 2],     ah[mf], b0, b2);
                        mma_fp16(acc[mf][nh * 4 + pr * 2 + 1], ah[mf], b1, b3);
                    }
                }
            }
        }
        __syncthreads();
        if (it + 3 < NC)
            g_load_stage(sb, A, W, m0, n0, K, (it + 3) * BK, tid);
        slot = (slot == NSTG - 1) ? 0 : slot + 1;
    }

    int r0 = m0 + warp_m + (lane >> 2);
    #pragma unroll
    for (int mf = 0; mf < 2; mf++) {
        #pragma unroll
        for (int nf = 0; nf < 8; nf++) {
            int col = n0 + warp_n + nf * 8 + (lane & 3) * 2;
            float bx = __ldg(bias + col), by = __ldg(bias + col + 1);
            #pragma unroll
            for (int half = 0; half < 2; half++) {
                int row = r0 + mf * 16 + half * 8;
                float v0 = acc[mf][nf][half * 2]     + bx;
                float v1 = acc[mf][nf][half * 2 + 1] + by;
                size_t base = (size_t)row * N + col;
                if (MODE == 1) {
                    v0 = gelu_t(v0); v1 = gelu_t(v1);
                    *(__half2*)(Ch + base) = __floats2half2_rn(v0, v1);
                } else if (MODE == 4) {
                    *(__half2*)(Ch + base) = __floats2half2_rn(v0, v1);
                } else {
                    if (MODE == 2) {
                        float2 rr = *(const float2*)(res + base);
                        v0 += rr.x; v1 += rr.y;
                    }
                    *(float2*)(Cf + base) = make_float2(v0, v1);
                }
            }
        }
    }
}

// ---------------------------------------------------------------------------
// fp32 SGEMM for the tiny merge GEMM (K=64)
// ---------------------------------------------------------------------------
__global__ __launch_bounds__(256) void sgemm_k(
    const float* __restrict__ A, const float* __restrict__ W,
    float* __restrict__ C, int M, int N, int K) {
    __shared__ float As[16][64];
    __shared__ float Bs[16][64];
    int tid = threadIdx.x;
    int m0 = blockIdx.y * 64, n0 = blockIdx.x * 64;
    int tx = tid & 15, ty = tid >> 4;
    int lr = tid >> 2;
    int lk = (tid & 3) * 4;
    const float* Ap = A + (size_t)(m0 + lr) * K + lk;
    const float* Wp = W + (size_t)(n0 + lr) * K + lk;
    float acc[4][4];
    #pragma unroll
    for (int i = 0; i < 4; i++)
        #pragma unroll
        for (int j = 0; j < 4; j++) acc[i][j] = 0.f;
    for (int k0 = 0; k0 < K; k0 += 16) {
        float4 av = *(const float4*)(Ap + k0);
        float4 bv = *(const float4*)(Wp + k0);
        As[lk + 0][lr] = av.x; As[lk + 1][lr] = av.y;
        As[lk + 2][lr] = av.z; As[lk + 3][lr] = av.w;
        Bs[lk + 0][lr] = bv.x; Bs[lk + 1][lr] = bv.y;
        Bs[lk + 2][lr] = bv.z; Bs[lk + 3][lr] = bv.w;
        __syncthreads();
        #pragma unroll
        for (int k = 0; k < 16; k++) {
            float4 a = *(const float4*)&As[k][ty * 4];
            float4 b = *(const float4*)&Bs[k][tx * 4];
            acc[0][0] += a.x * b.x; acc[0][1] += a.x * b.y; acc[0][2] += a.x * b.z; acc[0][3] += a.x * b.w;
            acc[1][0] += a.y * b.x; acc[1][1] += a.y * b.y; acc[1][2] += a.y * b.z; acc[1][3] += a.y * b.w;
            acc[2][0] += a.z * b.x; acc[2][1] += a.z * b.y; acc[2][2] += a.z * b.z; acc[2][3] += a.z * b.w;
            acc[3][0] += a.w * b.x; acc[3][1] += a.w * b.y; acc[3][2] += a.w * b.z; acc[3][3] += a.w * b.w;
        }
        __syncthreads();
    }
    #pragma unroll
    for (int i = 0; i < 4; i++) {
        int m = m0 + ty * 4 + i;
        *(float4*)(C + (size_t)m * N + n0 + tx * 4) =
            make_float4(acc[i][0], acc[i][1], acc[i][2], acc[i][3]);
    }
}

// ---------------------------------------------------------------------------
// 2D RoPE, in-place on fp16 qkv (q scaled 1/8, q/k rotated; v untouched).
// One block per token; sincos deduped via smem.
// ---------------------------------------------------------------------------
__global__ __launch_bounds__(256) void rope_h_k(__half* __restrict__ qh) {
    __shared__ float scache[4][16];
    int tid = threadIdx.x;
    int tok = blockIdx.x;
    int l = tok & (L - 1);
    if (tid < 16) {
        float inv = powf(10000.0f, -(float)tid * (1.0f / 16.0f));
        float s1, c1, s2, c2;
        sincosf((float)(l >> 5) * inv, &s1, &c1);
        sincosf((float)(l & 31) * inv, &s2, &c2);
        scache[0][tid] = s1; scache[1][tid] = c1;
        scache[2][tid] = s2; scache[3][tid] = c2;
    }
    __syncthreads();
    int t = tid & 15;
    int h = tid >> 4;
    float s1 = scache[0][t], c1 = scache[1][t];
    float s2 = scache[2][t], c2 = scache[3][t];
    __half* base = qh + (size_t)tok * D3 + h * DH;
    {   // q: rope + scale 1/8
        __half* p = base;
        float x0 = __half2float(p[t]), x1 = __half2float(p[t + 16]);
        p[t]      = __float2half((x0 * c1 - x1 * s1) * 0.125f);
        p[t + 16] = __float2half((x1 * c1 + x0 * s1) * 0.125f);
        float y0 = __half2float(p[t + 32]), y1 = __half2float(p[t + 48]);
        p[t + 32] = __float2half((y0 * c2 - y1 * s2) * 0.125f);
        p[t + 48] = __float2half((y1 * c2 + y0 * s2) * 0.125f);
    }
    {   // k: rope
        __half* p = base + D;
        float x0 = __half2float(p[t]), x1 = __half2float(p[t + 16]);
        p[t]      = __float2half(x0 * c1 - x1 * s1);
        p[t + 16] = __float2half(x1 * c1 + x0 * s1);
        float y0 = __half2float(p[t + 32]), y1 = __half2float(p[t + 48]);
        p[t + 32] = __float2half(y0 * c2 - y1 * s2);
        p[t + 48] = __float2half(y1 * c2 + y0 * s2);
    }
}

// ---------------------------------------------------------------------------
// HMMA flash attention (fp16 inputs, fp32 accum) -> fp16 output.
// ---------------------------------------------------------------------------
#define APADB 144
#define AQ_B  (128 * APADB)
#define AKV_B (64 * APADB)
#define ASTG_B (2 * AKV_B)
#define ATT_SMEM (AQ_B + 2 * ASTG_B)

__global__ __launch_bounds__(256) void attn_mma_k(const __half* __restrict__ qkvh,
                                                  __half* __restrict__ oh) {
    extern __shared__ char attsm[];
    uint32_t sb0 = smem_u32(attsm);
    int tid = threadIdx.x, lane = tid & 31, warp = tid >> 5;
    int h = blockIdx.y, n = blockIdx.z;
    int q0 = blockIdx.x * 128;

    const __half* qbase = qkvh + ((size_t)(n * L + q0)) * D3 + h * DH;
    const __half* kbase = qkvh + (size_t)n * L * D3 + D + h * DH;
    const __half* vbase = kbase + D;

    for (int i = tid; i < 1024; i += 256) {
        int r = i >> 3, g = i & 7;
        cp_async16(sb0 + (uint32_t)r * APADB + g * 16, qbase + (size_t)r * D3 + g * 8);
    }
    cp_commit();

    auto load_kv = [&](int t) {
        uint32_t s = sb0 + AQ_B + (uint32_t)(t & 1) * ASTG_B;
        const __half* kb = kbase + (size_t)(t * 64) * D3;
        const __half* vb = vbase + (size_t)(t * 64) * D3;
        for (int i = tid; i < 512; i += 256) {
            int r = i >> 3, g = i & 7;
            uint32_t off = (uint32_t)r * APADB + g * 16;
            cp_async16(s + off,         kb + (size_t)r * D3 + g * 8);
            cp_async16(s + AKV_B + off, vb + (size_t)r * D3 + g * 8);
        }
        cp_commit();
    };
    load_kv(0);
    load_kv(1);
    cp_wait<2>();
    __syncthreads();

    uint32_t qf[4][4];
    {
        uint32_t qrow = (uint32_t)(warp * 16 + (lane & 15));
        uint32_t kseg = (uint32_t)(lane >> 4) * 16;
        #pragma unroll
        for (int ks = 0; ks < 4; ks++)
            ldmx4(sb0 + qrow * APADB + kseg + ks * 32,
                  qf[ks][0], qf[ks][1], qf[ks][2], qf[ks][3]);
    }

    float m0 = -1e30f, m1 = -1e30f, l0 = 0.f, l1 = 0.f;
    float oacc[8][4];
    #pragma unroll
    for (int f = 0; f < 8; f++)
        #pragma unroll
        for (int c = 0; c < 4; c++) oacc[f][c] = 0.f;

    for (int t = 0; t < 16; t++) {
        uint32_t s = sb0 + AQ_B + (uint32_t)(t & 1) * ASTG_B;
        if (t + 1 < 16) cp_wait<1>(); else cp_wait<0>();
        __syncthreads();

        float sc[8][4];
        #pragma unroll
        for (int f = 0; f < 8; f++)
            #pragma unroll
            for (int c = 0; c < 4; c++) sc[f][c] = 0.f;

        #pragma unroll
        for (int ks = 0; ks < 4; ks++) {
            #pragma unroll
            for (int sg = 0; sg < 4; sg++) {
                uint32_t addr = s + (uint32_t)(sg * 16 + (lane & 15)) * APADB +
                                (uint32_t)(lane >> 4) * 16 + ks * 32;
                uint32_t b0, b1, b2, b3;
                ldmx4(addr, b0, b1, b2, b3);
                mma_fp16(sc[sg * 2],     qf[ks], b0, b2);
                mma_fp16(sc[sg * 2 + 1], qf[ks], b1, b3);
            }
        }

        float rmax0 = -1e30f, rmax1 = -1e30f;
        #pragma unroll
        for (int f = 0; f < 8; f++) {
            rmax0 = fmaxf(rmax0, fmaxf(sc[f][0], sc[f][1]));
            rmax1 = fmaxf(rmax1, fmaxf(sc[f][2], sc[f][3]));
        }
        rmax0 = fmaxf(rmax0, __shfl_xor_sync(0xffffffffu, rmax0, 1));
        rmax0 = fmaxf(rmax0, __shfl_xor_sync(0xffffffffu, rmax0, 2));
        rmax1 = fmaxf(rmax1, __shfl_xor_sync(0xffffffffu, rmax1, 1));
        rmax1 = fmaxf(rmax1, __shfl_xor_sync(0xffffffffu, rmax1, 2));
        float mn0 = fmaxf(m0, rmax0), mn1 = fmaxf(m1, rmax1);
        float sf0 = __expf(m0 - mn0), sf1 = __expf(m1 - mn1);
        m0 = mn0; m1 = mn1;
        l0 *= sf0; l1 *= sf1;
        #pragma unroll
        for (int f = 0; f < 8; f++) {
            oacc[f][0] *= sf0; oacc[f][1] *= sf0;
            oacc[f][2] *= sf1; oacc[f][3] *= sf1;
        }
        float rs0 = 0.f, rs1 = 0.f;
        #pragma unroll
        for (int f = 0; f < 8; f++) {
            sc[f][0] = __expf(sc[f][0] - m0);
            sc[f][1] = __expf(sc[f][1] - m0);
            sc[f][2] = __expf(sc[f][2] - m1);
            sc[f][3] = __expf(sc[f][3] - m1);
            rs0 += sc[f][0] + sc[f][1];
            rs1 += sc[f][2] + sc[f][3];
        }
        rs0 += __shfl_xor_sync(0xffffffffu, rs0, 1);
        rs0 += __shfl_xor_sync(0xffffffffu, rs0, 2);
        rs1 += __shfl_xor_sync(0xffffffffu, rs1, 1);
        rs1 += __shfl_xor_sync(0xffffffffu, rs1, 2);
        l0 += rs0; l1 += rs1;

        uint32_t pa[4][4];
        #pragma unroll
        for (int j = 0; j < 4; j++) {
            pa[j][0] = packh2(sc[2 * j][0],     sc[2 * j][1]);
            pa[j][1] = packh2(sc[2 * j][2],     sc[2 * j][3]);
            pa[j][2] = packh2(sc[2 * j + 1][0], sc[2 * j + 1][1]);
            pa[j][3] = packh2(sc[2 * j + 1][2], sc[2 * j + 1][3]);
        }

        uint32_t vb = s + AKV_B;
        #pragma unroll
        for (int j = 0; j < 4; j++) {
            #pragma unroll
            for (int dseg = 0; dseg < 4; dseg++) {
                uint32_t addr = vb + (uint32_t)(j * 16 + (lane & 15)) * APADB +
                                (uint32_t)(lane >> 4) * 16 + dseg * 32;
                uint32_t b0, b1, b2, b3;
                ldmx4t(addr, b0, b1, b2, b3);
                mma_fp16(oacc[dseg * 2],     pa[j], b0, b1);
                mma_fp16(oacc[dseg * 2 + 1], pa[j], b2, b3);
            }
        }
        __syncthreads();
        if (t + 2 < 16) load_kv(t + 2);
    }

    float inv0 = 1.0f / l0, inv1 = 1.0f / l1;
    int row0 = q0 + warp * 16 + (lane >> 2);
    #pragma unroll
    for (int f = 0; f < 8; f++) {
        int col = h * DH + f * 8 + (lane & 3) * 2;
        #pragma unroll
        for (int half = 0; half < 2; half++) {
            int row = row0 + half * 8;
            float v0 = oacc[f][half * 2]     * (half ? inv1 : inv0);
            float v1 = oacc[f][half * 2 + 1] * (half ? inv1 : inv0);
            size_t base = ((size_t)(n * L + row)) * D + col;
            *(__half2*)(oh + base) = __floats2half2_rn(v0, v1);
        }
    }
}

// ---------------------------------------------------------------------------
// Transpose [N, L, D] -> [N, D, L]
// ---------------------------------------------------------------------------
__global__ void transpose_k(const float* __restrict__ in, float* __restrict__ out) {
    __shared__ float tile[32][33];
    int n = blockIdx.z;
    int l0 = blockIdx.x * 32, d0 = blockIdx.y * 32;
    int tx = threadIdx.x, ty = threadIdx.y;
    #pragma unroll
    for (int i = ty; i < 32; i += 8)
        tile[i][tx] = in[((size_t)(n * L + l0 + i)) * D + d0 + tx];
    __syncthreads();
    #pragma unroll
    for (int i = ty; i < 32; i += 8)
        out[((size_t)(n * D + d0 + i)) * L + l0 + tx] = tile[tx][i];
}

// ---------------------------------------------------------------------------
// Launch
// ---------------------------------------------------------------------------
extern "C" void kernel_launch(void* const* d_in, const int* in_sizes, int n_in,
                              void* d_out, int out_size) {
    const float* x       = (const float*)d_in[0];
    const float* merge_w = (const float*)d_in[1];
    const float* qkv_w   = (const float*)d_in[2];
    const float* qkv_b   = (const float*)d_in[3];
    const float* proj_w  = (const float*)d_in[4];
    const float* proj_b  = (const float*)d_in[5];
    const float* fc1_w   = (const float*)d_in[6];
    const float* fc1_b   = (const float*)d_in[7];
    const float* fc2_w   = (const float*)d_in[8];
    const float* fc2_b   = (const float*)d_in[9];
    float* out = (float*)d_out;

    float *patch, *tok, *hbuf;
    __half *qkvh, *h_h, *att_h, *mlp_h;
    __half *wqkv_h, *wproj_h, *wfc1_h, *wfc2_h;
    cudaGetSymbolAddress((void**)&patch,  g_patch);
    cudaGetSymbolAddress((void**)&tok,    g_tok);
    cudaGetSymbolAddress((void**)&hbuf,   g_h);
    cudaGetSymbolAddress((void**)&qkvh,   g_qkvh);
    cudaGetSymbolAddress((void**)&h_h,    g_h_h);
    cudaGetSymbolAddress((void**)&att_h,  g_att_h);
    cudaGetSymbolAddress((void**)&mlp_h,  g_mlp_h);
    cudaGetSymbolAddress((void**)&wqkv_h, g_wqkv_h);
    cudaGetSymbolAddress((void**)&wproj_h, g_wproj_h);
    cudaGetSymbolAddress((void**)&wfc1_h, g_wfc1_h);
    cudaGetSymbolAddress((void**)&wfc2_h, g_wfc2_h);

    cudaFuncSetAttribute(hgemm_k<1>, cudaFuncAttributeMaxDynamicSharedMemorySize, GSMEM);
    cudaFuncSetAttribute(hgemm_k<2>, cudaFuncAttributeMaxDynamicSharedMemorySize, GSMEM);
    cudaFuncSetAttribute(hgemm_k<4>, cudaFuncAttributeMaxDynamicSharedMemorySize, GSMEM);
    cudaFuncSetAttribute(attn_mma_k, cudaFuncAttributeMaxDynamicSharedMemorySize, ATT_SMEM);

    // Convert weights to fp16
    cvt_h_k<<<(DEPTH * D3 * D / 4 + 255) / 256, 256>>>(
        (const float4*)qkv_w, (__half2*)wqkv_h, DEPTH * D3 * D / 4);
    cvt_h_k<<<(DEPTH * D * D / 4 + 255) / 256, 256>>>(
        (const float4*)proj_w, (__half2*)wproj_h, DEPTH * D * D / 4);
    cvt_h_k<<<(DEPTH * D4 * D / 4 + 255) / 256, 256>>>(
        (const float4*)fc1_w, (__half2*)wfc1_h, DEPTH * D4 * D / 4);
    cvt_h_k<<<(DEPTH * D * D4 / 4 + 255) / 256, 256>>>(
        (const float4*)fc2_w, (__half2*)wfc2_h, DEPTH * D * D4 / 4);

    patch_gather_k<<<(TOK * 64 + 255) / 256, 256>>>(x, patch);
    sgemm_k<<<dim3(D / 64, TOK / 64), 256>>>(patch, merge_w, tok, TOK, D, 64);

    for (int i = 0; i < DEPTH; i++) {
        // attention block: QKV GEMM -> fp16, then in-place RoPE on q,k
        rmsnorm_h_k<<<TOK, 256>>>(tok, h_h);
        hgemm_k<4><<<dim3(D3 / BN, TOK / BM), 256, GSMEM>>>(
            h_h, wqkv_h + (size_t)i * D3 * D,
            qkv_b + (size_t)i * D3, nullptr, nullptr, qkvh, D3, D);
        rope_h_k<<<TOK, 256>>>(qkvh);
        attn_mma_k<<<dim3(L / 128, HEADS, NB), 256, ATT_SMEM>>>(qkvh, att_h);
        hgemm_k<2><<<dim3(D / BN, TOK / BM), 256, GSMEM>>>(
            att_h, wproj_h + (size_t)i * D * D,
            proj_b + (size_t)i * D, tok, tok, nullptr, D, D);
        // MLP block
        rmsnorm_h_k<<<TOK, 256>>>(tok, h_h);
        hgemm_k<1><<<dim3(D4 / BN, TOK / BM), 256, GSMEM>>>(
            h_h, wfc1_h + (size_t)i * D4 * D,
            fc1_b + (size_t)i * D4, nullptr, nullptr, mlp_h, D4, D);
        hgemm_k<2><<<dim3(D / BN, TOK / BM), 256, GSMEM>>>(
            mlp_h, wfc2_h + (size_t)i * D * D4,
            fc2_b + (size_t)i * D, tok, tok, nullptr, D, D4);
    }

    rmsnorm_k<<<TOK, 256>>>(tok, hbuf);
    transpose_k<<<dim3(L / 32, D / 32, NB), dim3(32, 8)>>>(hbuf, out);
}

// round 17
// speedup vs baseline: 1.5475x; 1.0314x over previous
#include <cuda_runtime.h>
#include <cuda_bf16.h>
#include <cuda_fp16.h>
#include <cstdint>
#include <cstdio>

// ---------------------------------------------------------------------------
// Problem constants
// ---------------------------------------------------------------------------
#define NB    4
#define CIN   16
#define HIN   64
#define WIN   64
#define HF    32
#define WF    32
#define L     1024
#define D     1024
#define HEADS 16
#define DH    64
#define DEPTH 8
#define TOK   (NB*L)       // 4096
#define D3    (3*D)        // 3072
#define D4    (4*D)        // 4096

// ---------------------------------------------------------------------------
// Scratch (static device globals; no runtime allocation)
// ---------------------------------------------------------------------------
__device__ float g_patch[TOK * 64];
__device__ float g_tok  [TOK * D];
__device__ float g_scale[TOK];
__device__ __half g_qkvh[TOK * D3];

__device__ __half g_h_h  [TOK * D];     // fp16 rmsnorm output (GEMM A)
__device__ __half g_att_h[TOK * D];     // fp16 attention output
__device__ __half g_mlp_h[TOK * D4];    // fp16 gelu(fc1) output

// fp16 weights (all depths)
__device__ __half g_wqkv_h[DEPTH * D3 * D];
__device__ __half g_wproj_h[DEPTH * D * D];
__device__ __half g_wfc1_h[DEPTH * D4 * D];
__device__ __half g_wfc2_h[DEPTH * D * D4];

// ---------------------------------------------------------------------------
// Helpers
// ---------------------------------------------------------------------------
__device__ __forceinline__ uint32_t smem_u32(const void* p) {
    uint32_t a;
    asm("{ .reg .u64 t; cvta.to.shared.u64 t, %1; cvt.u32.u64 %0, t; }" : "=r"(a) : "l"(p));
    return a;
}
__device__ __forceinline__ void cp_async16(uint32_t s, const void* g) {
    asm volatile("cp.async.cg.shared.global [%0], [%1], 16;" :: "r"(s), "l"(g));
}
__device__ __forceinline__ void cp_commit() { asm volatile("cp.async.commit_group;"); }
template <int N> __device__ __forceinline__ void cp_wait() {
    asm volatile("cp.async.wait_group %0;" :: "n"(N));
}
__device__ __forceinline__ void ldmx4(uint32_t a, uint32_t& d0, uint32_t& d1,
                                      uint32_t& d2, uint32_t& d3) {
    asm volatile("ldmatrix.sync.aligned.m8n8.x4.shared.b16 {%0,%1,%2,%3}, [%4];"
                 : "=r"(d0), "=r"(d1), "=r"(d2), "=r"(d3) : "r"(a));
}
__device__ __forceinline__ void ldmx4t(uint32_t a, uint32_t& d0, uint32_t& d1,
                                       uint32_t& d2, uint32_t& d3) {
    asm volatile("ldmatrix.sync.aligned.m8n8.x4.trans.shared.b16 {%0,%1,%2,%3}, [%4];"
                 : "=r"(d0), "=r"(d1), "=r"(d2), "=r"(d3) : "r"(a));
}
__device__ __forceinline__ void mma_fp16(float* c, const uint32_t* a,
                                         uint32_t b0, uint32_t b1) {
    asm volatile(
        "mma.sync.aligned.m16n8k16.row.col.f32.f16.f16.f32 "
        "{%0,%1,%2,%3}, {%4,%5,%6,%7}, {%8,%9}, {%0,%1,%2,%3};"
        : "+f"(c[0]), "+f"(c[1]), "+f"(c[2]), "+f"(c[3])
        : "r"(a[0]), "r"(a[1]), "r"(a[2]), "r"(a[3]), "r"(b0), "r"(b1));
}
__device__ __forceinline__ uint32_t packh2(float a, float b) {
    __half2 h = __floats2half2_rn(a, b);
    return *(uint32_t*)&h;
}
__device__ __forceinline__ float gelu_t(float x) {
    float x3 = x * x * x;
    float u = 0.7978845608028654f * (x + 0.044715f * x3);
    return 0.5f * x * (1.0f + tanhf(u));
}

// ---------------------------------------------------------------------------
// fp32 -> fp16 convert, float4-vectorized
// ---------------------------------------------------------------------------
__global__ void cvt_h_k(const float4* __restrict__ in, __half2* __restrict__ o, int n4) {
    int i = blockIdx.x * 256 + threadIdx.x;
    if (i >= n4) return;
    float4 v = in[i];
    o[2 * i]     = __floats2half2_rn(v.x, v.y);
    o[2 * i + 1] = __floats2half2_rn(v.z, v.w);
}

// ---------------------------------------------------------------------------
// Patch gather
// ---------------------------------------------------------------------------
__global__ void patch_gather_k(const float* __restrict__ x, float* __restrict__ patch) {
    int idx = blockIdx.x * 256 + threadIdx.x;
    if (idx >= TOK * 64) return;
    int k = idx & 63, t = idx >> 6;
    int n = t >> 10, l = t & (L - 1);
    int hf = l >> 5, wf = l & 31;
    int c = k >> 2, kh = (k >> 1) & 1, kw = k & 1;
    patch[idx] = x[((n * CIN + c) * HIN + (hf * 2 + kh)) * WIN + (wf * 2 + kw)];
}

// ---------------------------------------------------------------------------
// RMSNorm
// ---------------------------------------------------------------------------
__device__ __forceinline__ float rms_row_scale(const float4 v, int tid) {
    float ss = v.x * v.x + v.y * v.y + v.z * v.z + v.w * v.w;
    #pragma unroll
    for (int o = 16; o; o >>= 1) ss += __shfl_xor_sync(0xffffffffu, ss, o);
    __shared__ float ws[8];
    if ((tid & 31) == 0) ws[tid >> 5] = ss;
    __syncthreads();
    float tot = 0.f;
    #pragma unroll
    for (int i = 0; i < 8; i++) tot += ws[i];
    return rsqrtf(tot * (1.0f / (float)D) + 1e-6f);
}

__global__ __launch_bounds__(256) void rmsnorm_h_k(const float* __restrict__ in,
                                                   __half* __restrict__ out) {
    int row = blockIdx.x;
    float4 v = ((const float4*)(in + (size_t)row * D))[threadIdx.x];
    float r = rms_row_scale(v, threadIdx.x);
    size_t base = (size_t)row * D + threadIdx.x * 4;
    *(__half2*)(out + base)     = __floats2half2_rn(v.x * r, v.y * r);
    *(__half2*)(out + base + 2) = __floats2half2_rn(v.z * r, v.w * r);
}

// Row scales only (for fused final rmsnorm+transpose)
__global__ __launch_bounds__(256) void rms_scale_k(const float* __restrict__ in,
                                                   float* __restrict__ scale) {
    int row = blockIdx.x;
    float4 v = ((const float4*)(in + (size_t)row * D))[threadIdx.x];
    float r = rms_row_scale(v, threadIdx.x);
    if (threadIdx.x == 0) scale[row] = r;
}

// ---------------------------------------------------------------------------
// fp16 tensor-core GEMM (R12/R15-proven config): C = A[M,K] @ W[N,K]^T
// BM=128, BN=128, 256 thr, 8 warps (32x64), 2 CTAs/SM, 80B padded smem rows.
// 4 sub-stage buffers of BK=32; TWO sub-stages processed per barrier pair
// (super-iteration = 64 K-elems) -> half the __syncthreads of R15.
// MODE 1: fp16 = gelu(acc+bias). MODE 2: fp32 = res+acc+bias. MODE 4: fp16 = acc+bias.
// ---------------------------------------------------------------------------
#define BM 128
#define BN 128
#define BK 32
#define PADK 40
#define ROWB (PADK * 2)                 // 80 bytes
#define MATB (BM * ROWB)                // 10240 B per matrix
#define STGB (2 * MATB)                 // 20480 B per sub-stage (A, W)
#define NSTG 4
#define GSMEM (NSTG * STGB)             // 81920 B -> 2 CTAs/SM

__device__ __forceinline__ void g_load_stage(
    uint32_t sb, const __half* __restrict__ A, const __half* __restrict__ B,
    int m0, int n0, int K, int k0, int tid)
{
    #pragma unroll
    for (int i = tid; i < 512; i += 256) {
        int r = i >> 2, c = i & 3;
        uint32_t off = (uint32_t)r * ROWB + (uint32_t)c * 16;
        size_t ga = (size_t)(m0 + r) * K + k0 + c * 8;
        size_t gb = (size_t)(n0 + r) * K + k0 + c * 8;
        cp_async16(sb + off,        A + ga);
        cp_async16(sb + MATB + off, B + gb);
    }
    cp_commit();
}

template <int MODE>
__global__ __launch_bounds__(256, 2)
void hgemm_k(const __half* __restrict__ A, const __half* __restrict__ W,
             const float* __restrict__ bias, const float* res,
             float* Cf, __half* Ch, int N, int K)
{
    extern __shared__ char dsm[];
    uint32_t sbase = smem_u32(dsm);
    int tid = threadIdx.x, lane = tid & 31, warp = tid >> 5;
    int m0 = blockIdx.y * BM, n0 = blockIdx.x * BN;
    int warp_m = (warp & 3) * 32;
    int warp_n = (warp >> 2) * 64;

    float acc[2][8][4];
    #pragma unroll
    for (int a = 0; a < 2; a++)
        #pragma unroll
        for (int b = 0; b < 8; b++)
            #pragma unroll
            for (int c = 0; c < 4; c++) acc[a][b][c] = 0.f;

    uint32_t a_row = (uint32_t)(warp_m + (lane & 15));
    uint32_t a_koff = (uint32_t)(lane >> 4) * 16;

    // one BK=32 sub-stage of compute (identical to R15 inner body)
    auto process = [&](uint32_t sb) {
        #pragma unroll
        for (int k16 = 0; k16 < 2; k16++) {
            uint32_t kb = (uint32_t)k16 * 32 + a_koff;
            uint32_t ah[2][4];
            #pragma unroll
            for (int mf = 0; mf < 2; mf++) {
                uint32_t ra = sb + (a_row + mf * 16) * ROWB + kb;
                ldmx4(ra, ah[mf][0], ah[mf][1], ah[mf][2], ah[mf][3]);
            }
            #pragma unroll
            for (int nh = 0; nh < 2; nh++) {
                #pragma unroll
                for (int pr = 0; pr < 2; pr++) {
                    uint32_t nrow = (uint32_t)(warp_n + nh * 32 + pr * 16 + (lane & 15));
                    uint32_t rb = sb + MATB + nrow * ROWB + kb;
                    uint32_t b0, b1, b2, b3;
                    ldmx4(rb, b0, b1, b2, b3);
                    #pragma unroll
                    for (int mf = 0; mf < 2; mf++) {
                        mma_fp16(acc[mf][nh * 4 + pr * 2],     ah[mf], b0, b2);
                        mma_fp16(acc[mf][nh * 4 + pr * 2 + 1], ah[mf], b1, b3);
                    }
                }
            }
        }
    };

    int NC2 = K / 64;                    // super-iterations (>= 16)
    // preload 4 sub-stages (= super-iters 0 and 1)
    g_load_stage(sbase,            A, W, m0, n0, K, 0,      tid);
    g_load_stage(sbase + STGB,     A, W, m0, n0, K, BK,     tid);
    g_load_stage(sbase + 2 * STGB, A, W, m0, n0, K, 2 * BK, tid);
    g_load_stage(sbase + 3 * STGB, A, W, m0, n0, K, 3 * BK, tid);

    for (int j = 0; j < NC2; j++) {
        uint32_t sbA = sbase + (uint32_t)((j & 1) * 2) * STGB;
        uint32_t sbB = sbA + STGB;
        if (j + 1 < NC2) cp_wait<2>(); else cp_wait<0>();
        __syncthreads();
        process(sbA);
        process(sbB);
        __syncthreads();
        if (j + 2 < NC2) {
            int k0 = (j + 2) * 64;
            g_load_stage(sbA, A, W, m0, n0, K, k0,      tid);
            g_load_stage(sbB, A, W, m0, n0, K, k0 + BK, tid);
        }
    }

    int r0 = m0 + warp_m + (lane >> 2);
    #pragma unroll
    for (int mf = 0; mf < 2; mf++) {
        #pragma unroll
        for (int nf = 0; nf < 8; nf++) {
            int col = n0 + warp_n + nf * 8 + (lane & 3) * 2;
            float bx = __ldg(bias + col), by = __ldg(bias + col + 1);
            #pragma unroll
            for (int half = 0; half < 2; half++) {
                int row = r0 + mf * 16 + half * 8;
                float v0 = acc[mf][nf][half * 2]     + bx;
                float v1 = acc[mf][nf][half * 2 + 1] + by;
                size_t base = (size_t)row * N + col;
                if (MODE == 1) {
                    v0 = gelu_t(v0); v1 = gelu_t(v1);
                    *(__half2*)(Ch + base) = __floats2half2_rn(v0, v1);
                } else if (MODE == 4) {
                    *(__half2*)(Ch + base) = __floats2half2_rn(v0, v1);
                } else {
                    if (MODE == 2) {
                        float2 rr = *(const float2*)(res + base);
                        v0 += rr.x; v1 += rr.y;
                    }
                    *(float2*)(Cf + base) = make_float2(v0, v1);
                }
            }
        }
    }
}

// ---------------------------------------------------------------------------
// fp32 SGEMM for the tiny merge GEMM (K=64)
// ---------------------------------------------------------------------------
__global__ __launch_bounds__(256) void sgemm_k(
    const float* __restrict__ A, const float* __restrict__ W,
    float* __restrict__ C, int M, int N, int K) {
    __shared__ float As[16][64];
    __shared__ float Bs[16][64];
    int tid = threadIdx.x;
    int m0 = blockIdx.y * 64, n0 = blockIdx.x * 64;
    int tx = tid & 15, ty = tid >> 4;
    int lr = tid >> 2;
    int lk = (tid & 3) * 4;
    const float* Ap = A + (size_t)(m0 + lr) * K + lk;
    const float* Wp = W + (size_t)(n0 + lr) * K + lk;
    float acc[4][4];
    #pragma unroll
    for (int i = 0; i < 4; i++)
        #pragma unroll
        for (int j = 0; j < 4; j++) acc[i][j] = 0.f;
    for (int k0 = 0; k0 < K; k0 += 16) {
        float4 av = *(const float4*)(Ap + k0);
        float4 bv = *(const float4*)(Wp + k0);
        As[lk + 0][lr] = av.x; As[lk + 1][lr] = av.y;
        As[lk + 2][lr] = av.z; As[lk + 3][lr] = av.w;
        Bs[lk + 0][lr] = bv.x; Bs[lk + 1][lr] = bv.y;
        Bs[lk + 2][lr] = bv.z; Bs[lk + 3][lr] = bv.w;
        __syncthreads();
        #pragma unroll
        for (int k = 0; k < 16; k++) {
            float4 a = *(const float4*)&As[k][ty * 4];
            float4 b = *(const float4*)&Bs[k][tx * 4];
            acc[0][0] += a.x * b.x; acc[0][1] += a.x * b.y; acc[0][2] += a.x * b.z; acc[0][3] += a.x * b.w;
            acc[1][0] += a.y * b.x; acc[1][1] += a.y * b.y; acc[1][2] += a.y * b.z; acc[1][3] += a.y * b.w;
            acc[2][0] += a.z * b.x; acc[2][1] += a.z * b.y; acc[2][2] += a.z * b.z; acc[2][3] += a.z * b.w;
            acc[3][0] += a.w * b.x; acc[3][1] += a.w * b.y; acc[3][2] += a.w * b.z; acc[3][3] += a.w * b.w;
        }
        __syncthreads();
    }
    #pragma unroll
    for (int i = 0; i < 4; i++) {
        int m = m0 + ty * 4 + i;
        *(float4*)(C + (size_t)m * N + n0 + tx * 4) =
            make_float4(acc[i][0], acc[i][1], acc[i][2], acc[i][3]);
    }
}

// ---------------------------------------------------------------------------
// 2D RoPE, in-place on fp16 qkv (q scaled 1/8, q/k rotated; v untouched).
// ---------------------------------------------------------------------------
__global__ __launch_bounds__(256) void rope_h_k(__half* __restrict__ qh) {
    __shared__ float scache[4][16];
    int tid = threadIdx.x;
    int tok = blockIdx.x;
    int l = tok & (L - 1);
    if (tid < 16) {
        float inv = powf(10000.0f, -(float)tid * (1.0f / 16.0f));
        float s1, c1, s2, c2;
        sincosf((float)(l >> 5) * inv, &s1, &c1);
        sincosf((float)(l & 31) * inv, &s2, &c2);
        scache[0][tid] = s1; scache[1][tid] = c1;
        scache[2][tid] = s2; scache[3][tid] = c2;
    }
    __syncthreads();
    int t = tid & 15;
    int h = tid >> 4;
    float s1 = scache[0][t], c1 = scache[1][t];
    float s2 = scache[2][t], c2 = scache[3][t];
    __half* base = qh + (size_t)tok * D3 + h * DH;
    {   // q: rope + scale 1/8
        __half* p = base;
        float x0 = __half2float(p[t]), x1 = __half2float(p[t + 16]);
        p[t]      = __float2half((x0 * c1 - x1 * s1) * 0.125f);
        p[t + 16] = __float2half((x1 * c1 + x0 * s1) * 0.125f);
        float y0 = __half2float(p[t + 32]), y1 = __half2float(p[t + 48]);
        p[t + 32] = __float2half((y0 * c2 - y1 * s2) * 0.125f);
        p[t + 48] = __float2half((y1 * c2 + y0 * s2) * 0.125f);
    }
    {   // k: rope
        __half* p = base + D;
        float x0 = __half2float(p[t]), x1 = __half2float(p[t + 16]);
        p[t]      = __float2half(x0 * c1 - x1 * s1);
        p[t + 16] = __float2half(x1 * c1 + x0 * s1);
        float y0 = __half2float(p[t + 32]), y1 = __half2float(p[t + 48]);
        p[t + 32] = __float2half(y0 * c2 - y1 * s2);
        p[t + 48] = __float2half(y1 * c2 + y0 * s2);
    }
}

// ---------------------------------------------------------------------------
// HMMA flash attention (fp16 inputs, fp32 accum) -> fp16 output.
// ---------------------------------------------------------------------------
#define APADB 144
#define AQ_B  (128 * APADB)
#define AKV_B (64 * APADB)
#define ASTG_B (2 * AKV_B)
#define ATT_SMEM (AQ_B + 2 * ASTG_B)

__global__ __launch_bounds__(256) void attn_mma_k(const __half* __restrict__ qkvh,
                                                  __half* __restrict__ oh) {
    extern __shared__ char attsm[];
    uint32_t sb0 = smem_u32(attsm);
    int tid = threadIdx.x, lane = tid & 31, warp = tid >> 5;
    int h = blockIdx.y, n = blockIdx.z;
    int q0 = blockIdx.x * 128;

    const __half* qbase = qkvh + ((size_t)(n * L + q0)) * D3 + h * DH;
    const __half* kbase = qkvh + (size_t)n * L * D3 + D + h * DH;
    const __half* vbase = kbase + D;

    for (int i = tid; i < 1024; i += 256) {
        int r = i >> 3, g = i & 7;
        cp_async16(sb0 + (uint32_t)r * APADB + g * 16, qbase + (size_t)r * D3 + g * 8);
    }
    cp_commit();

    auto load_kv = [&](int t) {
        uint32_t s = sb0 + AQ_B + (uint32_t)(t & 1) * ASTG_B;
        const __half* kb = kbase + (size_t)(t * 64) * D3;
        const __half* vb = vbase + (size_t)(t * 64) * D3;
        for (int i = tid; i < 512; i += 256) {
            int r = i >> 3, g = i & 7;
            uint32_t off = (uint32_t)r * APADB + g * 16;
            cp_async16(s + off,         kb + (size_t)r * D3 + g * 8);
            cp_async16(s + AKV_B + off, vb + (size_t)r * D3 + g * 8);
        }
        cp_commit();
    };
    load_kv(0);
    load_kv(1);
    cp_wait<2>();
    __syncthreads();

    uint32_t qf[4][4];
    {
        uint32_t qrow = (uint32_t)(warp * 16 + (lane & 15));
        uint32_t kseg = (uint32_t)(lane >> 4) * 16;
        #pragma unroll
        for (int ks = 0; ks < 4; ks++)
            ldmx4(sb0 + qrow * APADB + kseg + ks * 32,
                  qf[ks][0], qf[ks][1], qf[ks][2], qf[ks][3]);
    }

    float m0 = -1e30f, m1 = -1e30f, l0 = 0.f, l1 = 0.f;
    float oacc[8][4];
    #pragma unroll
    for (int f = 0; f < 8; f++)
        #pragma unroll
        for (int c = 0; c < 4; c++) oacc[f][c] = 0.f;

    for (int t = 0; t < 16; t++) {
        uint32_t s = sb0 + AQ_B + (uint32_t)(t & 1) * ASTG_B;
        if (t + 1 < 16) cp_wait<1>(); else cp_wait<0>();
        __syncthreads();

        float sc[8][4];
        #pragma unroll
        for (int f = 0; f < 8; f++)
            #pragma unroll
            for (int c = 0; c < 4; c++) sc[f][c] = 0.f;

        #pragma unroll
        for (int ks = 0; ks < 4; ks++) {
            #pragma unroll
            for (int sg = 0; sg < 4; sg++) {
                uint32_t addr = s + (uint32_t)(sg * 16 + (lane & 15)) * APADB +
                                (uint32_t)(lane >> 4) * 16 + ks * 32;
                uint32_t b0, b1, b2, b3;
                ldmx4(addr, b0, b1, b2, b3);
                mma_fp16(sc[sg * 2],     qf[ks], b0, b2);
                mma_fp16(sc[sg * 2 + 1], qf[ks], b1, b3);
            }
        }

        float rmax0 = -1e30f, rmax1 = -1e30f;
        #pragma unroll
        for (int f = 0; f < 8; f++) {
            rmax0 = fmaxf(rmax0, fmaxf(sc[f][0], sc[f][1]));
            rmax1 = fmaxf(rmax1, fmaxf(sc[f][2], sc[f][3]));
        }
        rmax0 = fmaxf(rmax0, __shfl_xor_sync(0xffffffffu, rmax0, 1));
        rmax0 = fmaxf(rmax0, __shfl_xor_sync(0xffffffffu, rmax0, 2));
        rmax1 = fmaxf(rmax1, __shfl_xor_sync(0xffffffffu, rmax1, 1));
        rmax1 = fmaxf(rmax1, __shfl_xor_sync(0xffffffffu, rmax1, 2));
        float mn0 = fmaxf(m0, rmax0), mn1 = fmaxf(m1, rmax1);
        float sf0 = __expf(m0 - mn0), sf1 = __expf(m1 - mn1);
        m0 = mn0; m1 = mn1;
        l0 *= sf0; l1 *= sf1;
        #pragma unroll
        for (int f = 0; f < 8; f++) {
            oacc[f][0] *= sf0; oacc[f][1] *= sf0;
            oacc[f][2] *= sf1; oacc[f][3] *= sf1;
        }
        float rs0 = 0.f, rs1 = 0.f;
        #pragma unroll
        for (int f = 0; f < 8; f++) {
            sc[f][0] = __expf(sc[f][0] - m0);
            sc[f][1] = __expf(sc[f][1] - m0);
            sc[f][2] = __expf(sc[f][2] - m1);
            sc[f][3] = __expf(sc[f][3] - m1);
            rs0 += sc[f][0] + sc[f][1];
            rs1 += sc[f][2] + sc[f][3];
        }
        rs0 += __shfl_xor_sync(0xffffffffu, rs0, 1);
        rs0 += __shfl_xor_sync(0xffffffffu, rs0, 2);
        rs1 += __shfl_xor_sync(0xffffffffu, rs1, 1);
        rs1 += __shfl_xor_sync(0xffffffffu, rs1, 2);
        l0 += rs0; l1 += rs1;

        uint32_t pa[4][4];
        #pragma unroll
        for (int j = 0; j < 4; j++) {
            pa[j][0] = packh2(sc[2 * j][0],     sc[2 * j][1]);
            pa[j][1] = packh2(sc[2 * j][2],     sc[2 * j][3]);
            pa[j][2] = packh2(sc[2 * j + 1][0], sc[2 * j + 1][1]);
            pa[j][3] = packh2(sc[2 * j + 1][2], sc[2 * j + 1][3]);
        }

        uint32_t vb = s + AKV_B;
        #pragma unroll
        for (int j = 0; j < 4; j++) {
            #pragma unroll
            for (int dseg = 0; dseg < 4; dseg++) {
                uint32_t addr = vb + (uint32_t)(j * 16 + (lane & 15)) * APADB +
                                (uint32_t)(lane >> 4) * 16 + dseg * 32;
                uint32_t b0, b1, b2, b3;
                ldmx4t(addr, b0, b1, b2, b3);
                mma_fp16(oacc[dseg * 2],     pa[j], b0, b1);
                mma_fp16(oacc[dseg * 2 + 1], pa[j], b2, b3);
            }
        }
        __syncthreads();
        if (t + 2 < 16) load_kv(t + 2);
    }

    float inv0 = 1.0f / l0, inv1 = 1.0f / l1;
    int row0 = q0 + warp * 16 + (lane >> 2);
    #pragma unroll
    for (int f = 0; f < 8; f++) {
        int col = h * DH + f * 8 + (lane & 3) * 2;
        #pragma unroll
        for (int half = 0; half < 2; half++) {
            int row = row0 + half * 8;
            float v0 = oacc[f][half * 2]     * (half ? inv1 : inv0);
            float v1 = oacc[f][half * 2 + 1] * (half ? inv1 : inv0);
            size_t base = ((size_t)(n * L + row)) * D + col;
            *(__half2*)(oh + base) = __floats2half2_rn(v0, v1);
        }
    }
}

// ---------------------------------------------------------------------------
// Fused scale + transpose: out[n][d][l] = tok[n][l][d] * scale[n*L+l]
// ---------------------------------------------------------------------------
__global__ void transpose_scaled_k(const float* __restrict__ in,
                                   const float* __restrict__ scale,
                                   float* __restrict__ out) {
    __shared__ float tile[32][33];
    int n = blockIdx.z;
    int l0 = blockIdx.x * 32, d0 = blockIdx.y * 32;
    int tx = threadIdx.x, ty = threadIdx.y;
    #pragma unroll
    for (int i = ty; i < 32; i += 8) {
        int row = n * L + l0 + i;
        tile[i][tx] = in[(size_t)row * D + d0 + tx] * scale[row];
    }
    __syncthreads();
    #pragma unroll
    for (int i = ty; i < 32; i += 8)
        out[((size_t)(n * D + d0 + i)) * L + l0 + tx] = tile[tx][i];
}

// ---------------------------------------------------------------------------
// Launch
// ---------------------------------------------------------------------------
extern "C" void kernel_launch(void* const* d_in, const int* in_sizes, int n_in,
                              void* d_out, int out_size) {
    const float* x       = (const float*)d_in[0];
    const float* merge_w = (const float*)d_in[1];
    const float* qkv_w   = (const float*)d_in[2];
    const float* qkv_b   = (const float*)d_in[3];
    const float* proj_w  = (const float*)d_in[4];
    const float* proj_b  = (const float*)d_in[5];
    const float* fc1_w   = (const float*)d_in[6];
    const float* fc1_b   = (const float*)d_in[7];
    const float* fc2_w   = (const float*)d_in[8];
    const float* fc2_b   = (const float*)d_in[9];
    float* out = (float*)d_out;

    float *patch, *tok, *scale;
    __half *qkvh, *h_h, *att_h, *mlp_h;
    __half *wqkv_h, *wproj_h, *wfc1_h, *wfc2_h;
    cudaGetSymbolAddress((void**)&patch,  g_patch);
    cudaGetSymbolAddress((void**)&tok,    g_tok);
    cudaGetSymbolAddress((void**)&scale,  g_scale);
    cudaGetSymbolAddress((void**)&qkvh,   g_qkvh);
    cudaGetSymbolAddress((void**)&h_h,    g_h_h);
    cudaGetSymbolAddress((void**)&att_h,  g_att_h);
    cudaGetSymbolAddress((void**)&mlp_h,  g_mlp_h);
    cudaGetSymbolAddress((void**)&wqkv_h, g_wqkv_h);
    cudaGetSymbolAddress((void**)&wproj_h, g_wproj_h);
    cudaGetSymbolAddress((void**)&wfc1_h, g_wfc1_h);
    cudaGetSymbolAddress((void**)&wfc2_h, g_wfc2_h);

    cudaFuncSetAttribute(hgemm_k<1>, cudaFuncAttributeMaxDynamicSharedMemorySize, GSMEM);
    cudaFuncSetAttribute(hgemm_k<2>, cudaFuncAttributeMaxDynamicSharedMemorySize, GSMEM);
    cudaFuncSetAttribute(hgemm_k<4>, cudaFuncAttributeMaxDynamicSharedMemorySize, GSMEM);
    cudaFuncSetAttribute(attn_mma_k, cudaFuncAttributeMaxDynamicSharedMemorySize, ATT_SMEM);

    // Convert weights to fp16
    cvt_h_k<<<(DEPTH * D3 * D / 4 + 255) / 256, 256>>>(
        (const float4*)qkv_w, (__half2*)wqkv_h, DEPTH * D3 * D / 4);
    cvt_h_k<<<(DEPTH * D * D / 4 + 255) / 256, 256>>>(
        (const float4*)proj_w, (__half2*)wproj_h, DEPTH * D * D / 4);
    cvt_h_k<<<(DEPTH * D4 * D / 4 + 255) / 256, 256>>>(
        (const float4*)fc1_w, (__half2*)wfc1_h, DEPTH * D4 * D / 4);
    cvt_h_k<<<(DEPTH * D * D4 / 4 + 255) / 256, 256>>>(
        (const float4*)fc2_w, (__half2*)wfc2_h, DEPTH * D * D4 / 4);

    patch_gather_k<<<(TOK * 64 + 255) / 256, 256>>>(x, patch);
    sgemm_k<<<dim3(D / 64, TOK / 64), 256>>>(patch, merge_w, tok, TOK, D, 64);

    for (int i = 0; i < DEPTH; i++) {
        // attention block: QKV GEMM -> fp16, then in-place RoPE on q,k
        rmsnorm_h_k<<<TOK, 256>>>(tok, h_h);
        hgemm_k<4><<<dim3(D3 / BN, TOK / BM), 256, GSMEM>>>(
            h_h, wqkv_h + (size_t)i * D3 * D,
            qkv_b + (size_t)i * D3, nullptr, nullptr, qkvh, D3, D);
        rope_h_k<<<TOK, 256>>>(qkvh);
        attn_mma_k<<<dim3(L / 128, HEADS, NB), 256, ATT_SMEM>>>(qkvh, att_h);
        hgemm_k<2><<<dim3(D / BN, TOK / BM), 256, GSMEM>>>(
            att_h, wproj_h + (size_t)i * D * D,
            proj_b + (size_t)i * D, tok, tok, nullptr, D, D);
        // MLP block
        rmsnorm_h_k<<<TOK, 256>>>(tok, h_h);
        hgemm_k<1><<<dim3(D4 / BN, TOK / BM), 256, GSMEM>>>(
            h_h, wfc1_h + (size_t)i * D4 * D,
            fc1_b + (size_t)i * D4, nullptr, nullptr, mlp_h, D4, D);
        hgemm_k<2><<<dim3(D / BN, TOK / BM), 256, GSMEM>>>(
            mlp_h, wfc2_h + (size_t)i * D * D4,
            fc2_b + (size_t)i * D, tok, tok, nullptr, D, D4);
    }

    // Final: row scales + fused scale-transpose to [N, D, L]
    rms_scale_k<<<TOK, 256>>>(tok, scale);
    transpose_scaled_k<<<dim3(L / 32, D / 32, NB), dim3(32, 8)>>>(tok, scale, out);
}